// round 7
// baseline (speedup 1.0000x reference)
#include <cuda_runtime.h>
#include <cuda_fp16.h>
#include <cuda_fp8.h>
#include <mma.h>
#include <math.h>

using namespace nvcuda;

#define NNODES 50000
#define EMAX   800000
#define E2MAX  (EMAX + NNODES)

// ---------------- device scratch ----------------
__device__ __align__(16) unsigned char g_xpq [NNODES * 256]; // fp8 features L1/L2 (4 heads x 64)
__device__ __align__(16) unsigned char g_xpq3[NNODES * 256]; // fp8 features L3 (4 heads x 40, padded to 64; pads stay 0)
__device__ __align__(16) __half g_xh [NNODES * 128];  // fp16 copy of input x
__device__ __align__(16) __half g_hh [NNODES * 64];   // fp16 hidden activations
__device__ __align__(16) float  g_as [NNODES * 4];
__device__ __align__(16) float  g_ad [NNODES * 4];
__device__ unsigned g_gmax[12];
__device__ int   g_cnt[NNODES];
__device__ int   g_rowstart[NNODES + 1];
__device__ int   g_esrc[E2MAX];
__device__ int   g_epos[E2MAX];
__device__ __align__(16) __half g_bcat1h[128 * 320];  // [W | W@a_s | W@a_d], zero-padded
__device__ __align__(16) __half g_bcat2h[64  * 320];
__device__ __align__(16) __half g_bcat3h[64  * 192];

__device__ __forceinline__ unsigned fenc(float f) {
    unsigned u = __float_as_uint(f);
    return (u & 0x80000000u) ? ~u : (u | 0x80000000u);
}
__device__ __forceinline__ float fdec(unsigned u) {
    u = (u & 0x80000000u) ? (u & 0x7fffffffu) : ~u;
    return __uint_as_float(u);
}
__device__ __forceinline__ __half2 cvt_fp8x2(unsigned short u) {
    __half2_raw r = __nv_cvt_fp8x2_to_halfraw2((__nv_fp8x2_storage_t)u, __NV_E4M3);
    return *reinterpret_cast<__half2*>(&r);
}

// ---------------- CSR build ----------------
__global__ void zero_counts_kernel() {
    int i = blockIdx.x * blockDim.x + threadIdx.x;
    if (i < NNODES) g_cnt[i] = 0;
    if (i < 12) g_gmax[i] = 0u;
}

__global__ void count_kernel(const int* __restrict__ ei, int E) {
    int e = blockIdx.x * blockDim.x + threadIdx.x;
    int e2 = E + NNODES;
    if (e >= e2) return;
    int dst = (e < E) ? ei[E + e] : (e - E);
    g_epos[e] = atomicAdd(&g_cnt[dst], 1);
}

#define SCHUNK ((NNODES + 1023) / 1024)
__global__ void scan_kernel() {
    __shared__ int wsum[32];
    int t = threadIdx.x;
    int lo = t * SCHUNK;
    int hi = min(lo + SCHUNK, NNODES);
    int sum = 0;
    for (int i = lo; i < hi; i++) sum += g_cnt[i];
    int lane = t & 31, w = t >> 5;
    int v = sum;
    #pragma unroll
    for (int o = 1; o < 32; o <<= 1) {
        int nv = __shfl_up_sync(0xffffffffu, v, o);
        if (lane >= o) v += nv;
    }
    if (lane == 31) wsum[w] = v;
    __syncthreads();
    if (w == 0) {
        int x = wsum[lane];
        #pragma unroll
        for (int o = 1; o < 32; o <<= 1) {
            int nv = __shfl_up_sync(0xffffffffu, x, o);
            if (lane >= o) x += nv;
        }
        wsum[lane] = x;
    }
    __syncthreads();
    int excl = v - sum + ((w > 0) ? wsum[w - 1] : 0);
    int run = excl;
    for (int i = lo; i < hi; i++) { g_rowstart[i] = run; run += g_cnt[i]; }
    if (hi == NNODES) g_rowstart[NNODES] = run;
}

__global__ void scatter_kernel(const int* __restrict__ ei, int E) {
    int e = blockIdx.x * blockDim.x + threadIdx.x;
    int e2 = E + NNODES;
    if (e >= e2) return;
    int src, dst;
    if (e < E) { src = ei[e]; dst = ei[E + e]; }
    else       { src = e - E; dst = src; }
    g_esrc[g_rowstart[dst] + g_epos[e]] = src;
}

// ---------------- x -> fp16 ----------------
__global__ void convx_kernel(const float* __restrict__ x) {
    int i = blockIdx.x * blockDim.x + threadIdx.x;
    if (i >= NNODES * 128 / 8) return;
    const float4* p = reinterpret_cast<const float4*>(x) + i * 2;
    float4 a = p[0], b = p[1];
    union { uint4 u; __half2 h[4]; } cv;
    cv.h[0] = __floats2half2_rn(a.x, a.y);
    cv.h[1] = __floats2half2_rn(a.z, a.w);
    cv.h[2] = __floats2half2_rn(b.x, b.y);
    cv.h[3] = __floats2half2_rn(b.z, b.w);
    *(reinterpret_cast<uint4*>(g_xh) + i) = cv.u;
}

// ---------------- Bcat = [W | W@a_s | W@a_d], fp16, zero-padded ----------------
template<int L>
__global__ void build_bcat_kernel(const float* __restrict__ W,
                                  const float* __restrict__ aw_s,
                                  const float* __restrict__ aw_d) {
    constexpr int K  = (L == 1) ? 128 : 64;
    constexpr int C  = (L == 3) ? 40 : 64;
    constexpr int HC = 4 * C;
    constexpr int Nc = HC + 8;
    constexpr int NP = (L == 3) ? 192 : 320;
    __half* bcat = (L == 1) ? g_bcat1h : (L == 2) ? g_bcat2h : g_bcat3h;
    int idx = blockIdx.x * blockDim.x + threadIdx.x;
    if (idx >= K * NP) return;
    int k = idx / NP, j = idx - k * NP;
    float v = 0.f;
    if (j < HC) {
        v = W[k * HC + j];
    } else if (j < Nc) {
        int t = j - HC;
        int h = t & 3;
        const float* a = (t >= 4) ? aw_d : aw_s;
        float sum = 0.f;
        #pragma unroll 4
        for (int c = 0; c < C; c++) sum = fmaf(W[k * HC + h * C + c], a[h * C + c], sum);
        v = sum;
    }
    bcat[idx] = __float2half_rn(v);
}

// ---------------- HGEMM (wmma): [xp(fp8) | g_as | g_ad] = A @ Bcat ----------------
template<int L>
__global__ __launch_bounds__(256) void hgemm_kernel() {
    constexpr int K  = (L == 1) ? 128 : 64;
    constexpr int C  = (L == 3) ? 40 : 64;
    constexpr int HC = 4 * C;
    constexpr int NP = (L == 3) ? 192 : 320;
    constexpr int M  = NNODES;
    const __half* __restrict__ A = (L == 1) ? g_xh : g_hh;
    const __half* __restrict__ B = (L == 1) ? g_bcat1h : (L == 2) ? g_bcat2h : g_bcat3h;

    __shared__ __align__(32) char smbuf[128 * 68 * 4];
    __half (*Ah)[24] = reinterpret_cast<__half(*)[24]>(smbuf);
    __half (*Bh)[72] = reinterpret_cast<__half(*)[72]>(smbuf + 128 * 24 * 2);
    float  (*Cs)[68] = reinterpret_cast<float(*)[68]>(smbuf);

    int tid  = threadIdx.x;
    int warp = tid >> 5, wm = warp >> 1, wn = warp & 1;
    int m0 = blockIdx.y * 128, n0 = blockIdx.x * 64;

    wmma::fragment<wmma::accumulator, 16, 16, 16, float> acc[2][2];
    #pragma unroll
    for (int i = 0; i < 2; i++)
        #pragma unroll
        for (int j = 0; j < 2; j++) wmma::fill_fragment(acc[i][j], 0.f);

    int ar = tid >> 1, acq = (tid & 1) * 8;
    int gm_a = m0 + ar;
    bool avalid = gm_a < M;
    const __half* aptr = A + (size_t)gm_a * K + acq;
    int bkr = tid >> 3, bnc = (tid & 7) * 8;
    const __half* bptr = B + (size_t)bkr * NP + n0 + bnc;

    for (int k0 = 0; k0 < K; k0 += 16) {
        uint4 va = make_uint4(0u, 0u, 0u, 0u);
        if (avalid) va = *reinterpret_cast<const uint4*>(aptr + k0);
        *reinterpret_cast<uint4*>(&Ah[ar][acq]) = va;
        if (tid < 128)
            *reinterpret_cast<uint4*>(&Bh[bkr][bnc]) =
                *reinterpret_cast<const uint4*>(bptr + (size_t)k0 * NP);
        __syncthreads();

        wmma::fragment<wmma::matrix_a, 16, 16, 16, __half, wmma::row_major> af;
        wmma::fragment<wmma::matrix_b, 16, 16, 16, __half, wmma::row_major> bf[2];
        #pragma unroll
        for (int j = 0; j < 2; j++)
            wmma::load_matrix_sync(bf[j], &Bh[0][wn * 32 + j * 16], 72);
        #pragma unroll
        for (int i = 0; i < 2; i++) {
            wmma::load_matrix_sync(af, &Ah[wm * 32 + i * 16][0], 24);
            #pragma unroll
            for (int j = 0; j < 2; j++)
                wmma::mma_sync(acc[i][j], af, bf[j], acc[i][j]);
        }
        __syncthreads();
    }

    #pragma unroll
    for (int i = 0; i < 2; i++)
        #pragma unroll
        for (int j = 0; j < 2; j++)
            wmma::store_matrix_sync(&Cs[wm * 32 + i * 16][wn * 32 + j * 16],
                                    acc[i][j], 68, wmma::mem_row_major);
    __syncthreads();

    #pragma unroll
    for (int pass = 0; pass < 4; pass++) {
        int row   = (tid >> 3) + pass * 32;
        int chunk = tid & 7;
        int gm = m0 + row;
        if (gm >= M) continue;
        int col0 = n0 + chunk * 8;
        float v[8];
        #pragma unroll
        for (int k = 0; k < 8; k++) v[k] = Cs[row][chunk * 8 + k];
        if (col0 < HC) {
            unsigned char b[8];
            #pragma unroll
            for (int k = 0; k < 8; k++)
                b[k] = (unsigned char)__nv_cvt_float_to_fp8(v[k], __NV_SATFINITE, __NV_E4M3);
            if constexpr (L != 3) {
                // feature layout = column layout (4 heads x 64)
                uint2 pk;
                pk.x = (unsigned)b[0] | ((unsigned)b[1] << 8) | ((unsigned)b[2] << 16) | ((unsigned)b[3] << 24);
                pk.y = (unsigned)b[4] | ((unsigned)b[5] << 8) | ((unsigned)b[6] << 16) | ((unsigned)b[7] << 24);
                *reinterpret_cast<uint2*>(g_xpq + (size_t)gm * 256 + col0) = pk;
            } else {
                // remap col j (4 heads x 40) -> padded (4 heads x 64); pads stay zero
                #pragma unroll
                for (int k = 0; k < 8; k++) {
                    int j = col0 + k;
                    int h = j / 40, c = j - h * 40;
                    g_xpq3[(size_t)gm * 256 + h * 64 + c] = b[k];
                }
            }
        } else if (col0 == HC) {
            *reinterpret_cast<float4*>(g_as + gm * 4) = make_float4(v[0], v[1], v[2], v[3]);
            *reinterpret_cast<float4*>(g_ad + gm * 4) = make_float4(v[4], v[5], v[6], v[7]);
        }
    }
}

// ---------------- per-head global max of g_as ----------------
__global__ void gmax_kernel(int base) {
    __shared__ unsigned sh[4];
    int t = threadIdx.x;
    if (t < 4) sh[t] = 0u;
    __syncthreads();
    int i = blockIdx.x * blockDim.x + t;
    unsigned v = 0u;
    if (i < NNODES * 4) v = fenc(g_as[i]);
    #pragma unroll
    for (int o = 4; o < 32; o <<= 1) v = max(v, __shfl_xor_sync(0xffffffffu, v, o));
    if ((t & 31) < 4) atomicMax(&sh[t & 3], v);
    __syncthreads();
    if (t < 4) atomicMax(&g_gmax[base + t], sh[t]);
}

// ---------------- aggregation: warp per dst node, fp8 gather + HFMA2 ----------------
// lane = h*8 + sub; lane covers 8 padded feature slots at h*64 + sub*8
template<int L, bool LOGSM, bool OUT_GH>
__global__ __launch_bounds__(256) void agg_kernel(const float* __restrict__ bias,
                                                  float* __restrict__ out_ext) {
    constexpr int C    = (L == 3) ? 40 : 64;
    constexpr int CSUB = C / 8;            // valid sub groups (8 or 5)
    int warp = (blockIdx.x * blockDim.x + threadIdx.x) >> 5;
    if (warp >= NNODES) return;
    int lane = threadIdx.x & 31;
    int h = lane >> 3, sub = lane & 7;
    int n = warp;

    const unsigned char* __restrict__ xq = (L == 3) ? g_xpq3 : g_xpq;
    size_t loff = (size_t)h * 64 + sub * 8;

    float adh = g_ad[n * 4 + h];
    float Mh  = fdec(g_gmax[(L - 1) * 4 + h]);
    float em  = Mh + adh;
    float stab = fmaxf(em, 0.2f * em);

    float s = 0.f;
    __half2 acch[4];
    #pragma unroll
    for (int k = 0; k < 4; k++) acch[k] = __floats2half2_rn(0.f, 0.f);

    #define FMA_FP8x8(PH, Q)                                               \
        {                                                                  \
            acch[0] = __hfma2(PH, cvt_fp8x2((unsigned short)(Q.x)), acch[0]);        \
            acch[1] = __hfma2(PH, cvt_fp8x2((unsigned short)((Q.x) >> 16)), acch[1]); \
            acch[2] = __hfma2(PH, cvt_fp8x2((unsigned short)(Q.y)), acch[2]);        \
            acch[3] = __hfma2(PH, cvt_fp8x2((unsigned short)((Q.y) >> 16)), acch[3]); \
        }

    int beg = g_rowstart[n], end = g_rowstart[n + 1];
    int i = beg;
    for (; i + 1 < end; i += 2) {
        int s0 = g_esrc[i], s1 = g_esrc[i + 1];
        float e0 = g_as[s0 * 4 + h] + adh;
        float e1 = g_as[s1 * 4 + h] + adh;
        uint2 q0 = *reinterpret_cast<const uint2*>(xq + (size_t)s0 * 256 + loff);
        uint2 q1 = *reinterpret_cast<const uint2*>(xq + (size_t)s1 * 256 + loff);
        e0 = fmaxf(e0, 0.2f * e0);
        e1 = fmaxf(e1, 0.2f * e1);
        float p0 = __expf(e0 - stab);
        float p1 = __expf(e1 - stab);
        s += p0 + p1;
        __half2 ph0 = __floats2half2_rn(p0, p0);
        __half2 ph1 = __floats2half2_rn(p1, p1);
        FMA_FP8x8(ph0, q0);
        FMA_FP8x8(ph1, q1);
    }
    if (i < end) {
        int s0 = g_esrc[i];
        float e0 = g_as[s0 * 4 + h] + adh;
        uint2 q0 = *reinterpret_cast<const uint2*>(xq + (size_t)s0 * 256 + loff);
        e0 = fmaxf(e0, 0.2f * e0);
        float p0 = __expf(e0 - stab);
        s += p0;
        __half2 ph0 = __floats2half2_rn(p0, p0);
        FMA_FP8x8(ph0, q0);
    }
    #undef FMA_FP8x8

    float acc[8];
    #pragma unroll
    for (int k = 0; k < 4; k++) {
        float2 f = __half22float2(acch[k]);
        acc[2 * k] = f.x; acc[2 * k + 1] = f.y;
    }

    bool valid = sub < CSUB;
    float inv_s = 1.f / s;
    float r[8];
    #pragma unroll
    for (int k = 0; k < 8; k++) {
        float v = acc[k] * inv_s;
        v += __shfl_xor_sync(0xffffffffu, v, 8);
        v += __shfl_xor_sync(0xffffffffu, v, 16);
        float bv = valid ? bias[sub * 8 + k] : 0.f;
        r[k] = fmaxf(0.25f * v + bv, 0.f);   // + bias, relu
    }
    if (LOGSM) {
        if (!valid) {
            #pragma unroll
            for (int k = 0; k < 8; k++) r[k] = -INFINITY;
        }
        float lm = r[0];
        #pragma unroll
        for (int k = 1; k < 8; k++) lm = fmaxf(lm, r[k]);
        #pragma unroll
        for (int o = 1; o < 8; o <<= 1) lm = fmaxf(lm, __shfl_xor_sync(0xffffffffu, lm, o));
        float le = 0.f;
        #pragma unroll
        for (int k = 0; k < 8; k++) le += __expf(r[k] - lm);
        #pragma unroll
        for (int o = 1; o < 8; o <<= 1) le += __shfl_xor_sync(0xffffffffu, le, o);
        float lse = lm + __logf(le);
        #pragma unroll
        for (int k = 0; k < 8; k++) r[k] -= lse;
    }
    if (h == 0 && valid) {
        if constexpr (OUT_GH) {
            union { uint4 u; __half2 h2[4]; } cv;
            cv.h2[0] = __floats2half2_rn(r[0], r[1]);
            cv.h2[1] = __floats2half2_rn(r[2], r[3]);
            cv.h2[2] = __floats2half2_rn(r[4], r[5]);
            cv.h2[3] = __floats2half2_rn(r[6], r[7]);
            *reinterpret_cast<uint4*>(g_hh + (size_t)n * 64 + sub * 8) = cv.u;
        } else {
            float* op = out_ext + (size_t)n * C + sub * 8;
            *reinterpret_cast<float4*>(op)     = make_float4(r[0], r[1], r[2], r[3]);
            *reinterpret_cast<float4*>(op + 4) = make_float4(r[4], r[5], r[6], r[7]);
        }
    }
}

// ---------------- host orchestration ----------------
extern "C" void kernel_launch(void* const* d_in, const int* in_sizes, int n_in,
                              void* d_out, int out_size)
{
    const float* x   = (const float*)d_in[0];
    const int*   ei  = (const int*)d_in[1];
    const float* W1  = (const float*)d_in[2];
    const float* as1 = (const float*)d_in[3];
    const float* ad1 = (const float*)d_in[4];
    const float* b1  = (const float*)d_in[5];
    const float* W2  = (const float*)d_in[6];
    const float* as2 = (const float*)d_in[7];
    const float* ad2 = (const float*)d_in[8];
    const float* b2  = (const float*)d_in[9];
    const float* W3  = (const float*)d_in[10];
    const float* as3 = (const float*)d_in[11];
    const float* ad3 = (const float*)d_in[12];
    const float* b3  = (const float*)d_in[13];
    float* out = (float*)d_out;

    int E  = in_sizes[1] / 2;
    int e2 = E + NNODES;

    zero_counts_kernel<<<(NNODES + 255) / 256, 256>>>();
    count_kernel<<<(e2 + 255) / 256, 256>>>(ei, E);
    scan_kernel<<<1, 1024>>>();
    scatter_kernel<<<(e2 + 255) / 256, 256>>>(ei, E);
    convx_kernel<<<(NNODES * 128 / 8 + 255) / 256, 256>>>(x);
    build_bcat_kernel<1><<<(128 * 320 + 255) / 256, 256>>>(W1, as1, ad1);
    build_bcat_kernel<2><<<(64  * 320 + 255) / 256, 256>>>(W2, as2, ad2);
    build_bcat_kernel<3><<<(64  * 192 + 255) / 256, 256>>>(W3, as3, ad3);

    const int AGG_GRID  = (NNODES + 7) / 8;
    const int GMAX_GRID = (NNODES * 4 + 255) / 256;
    const int MGRID     = (NNODES + 127) / 128;

    hgemm_kernel<1><<<dim3(5, MGRID), 256>>>();
    gmax_kernel<<<GMAX_GRID, 256>>>(0);
    agg_kernel<1, false, true><<<AGG_GRID, 256>>>(b1, out);

    hgemm_kernel<2><<<dim3(5, MGRID), 256>>>();
    gmax_kernel<<<GMAX_GRID, 256>>>(4);
    agg_kernel<2, false, true><<<AGG_GRID, 256>>>(b2, out);

    hgemm_kernel<3><<<dim3(3, MGRID), 256>>>();
    gmax_kernel<<<GMAX_GRID, 256>>>(8);
    agg_kernel<3, true, false><<<AGG_GRID, 256>>>(b3, out);
}